// round 15
// baseline (speedup 1.0000x reference)
#include <cuda_runtime.h>
#include <cstdint>
#include <cstddef>

#define BATCH 4
#define ZCH 64
#define ED 16
#define NEMB 16384
#define PCH 64
#define FRES 32
#define NPOS (BATCH*FRES*FRES)
#define NBT (NEMB/128)

// ---------------- scratch ----------------
__device__ float g_z[NPOS*ED];
__device__ float g_zz[NPOS];
__device__ float g_cnorm[NEMB];
__device__ float g_zl[BATCH*ED*FRES*FRES];
__device__ float g_h[NPOS*PCH];
__device__ float g_pv[(size_t)NPOS*NBT];
__device__ int   g_pi[(size_t)NPOS*NBT];
__device__ float g_pv2[(size_t)NPOS*NBT];
__device__ int   g_pi2[(size_t)NPOS*NBT];
__device__ int   g_vqidx[NPOS];
__device__ int   g_topidx[NPOS];
__device__ float g_dcin[BATCH*ZCH*FRES*FRES];
__device__ float g_d0[BATCH*ZCH*FRES*FRES];
__device__ float g_t[BATCH*ZCH*64*64];

typedef unsigned long long u64t;

__device__ __forceinline__ void fma2(u64t& d, u64t a, u64t b) {
    asm("fma.rn.f32x2 %0, %1, %2, %0;" : "+l"(d) : "l"(a), "l"(b));
}
__device__ __forceinline__ u64t dup2(float x) {
    u64t p;
    asm("mov.b64 %0, {%1, %1};" : "=l"(p) : "f"(x));
    return p;
}
__device__ __forceinline__ void unpack2(float& lo, float& hi, u64t p) {
    asm("mov.b64 {%0, %1}, %2;" : "=f"(lo), "=f"(hi) : "l"(p));
}

__device__ __forceinline__ float get_w(const void* wp) {
    int i = *(const int*)wp;
    float f = __int_as_float(i);
    float af = fabsf(f);
    if (af < 1e-20f) return (float)i;
    if (i > -100000000 && i < 100000000) return (float)i;
    return f;
}

// ---------------- cnorm ----------------
__global__ void k_cnorm(const float* __restrict__ cb) {
    int n = blockIdx.x * 256 + threadIdx.x;
    if (n < NEMB) {
        const float* r = cb + (size_t)n * ED;
        float s = 0.f;
        #pragma unroll
        for (int e = 0; e < ED; e++) s += r[e] * r[e];
        g_cnorm[n] = s;
    }
}

// ---------------- quant+lrq 1x1 convs ----------------
__global__ void __launch_bounds__(256) k_quant_lrq(
    const float* __restrict__ zt, const float* __restrict__ zlp,
    const float* __restrict__ qw, const float* __restrict__ qb,
    const float* __restrict__ lw, const float* __restrict__ lb,
    float* __restrict__ out_zl)
{
    __shared__ float sqw[ED*ZCH];
    __shared__ float slw[ED*ZCH];
    __shared__ float sq[64][4][17];
    __shared__ float sl[64][4][17];
    int tid = threadIdx.x;
    for (int i = tid; i < ED*ZCH; i += 256) { sqw[i] = qw[i]; slw[i] = lw[i]; }
    int pl = tid >> 2, cg = tid & 3;
    int pos = blockIdx.x * 64 + pl;
    int b = pos >> 10, rem = pos & 1023;
    size_t base = (size_t)b * ZCH * 1024 + rem;
    float q[ED], l[ED];
    #pragma unroll
    for (int e = 0; e < ED; e++) { q[e] = 0.f; l[e] = 0.f; }
    __syncthreads();
    #pragma unroll
    for (int cc = 0; cc < 16; cc++) {
        int c = cg * 16 + cc;
        float a  = zt[base + (size_t)c * 1024];
        float z2 = zlp[base + (size_t)c * 1024];
        #pragma unroll
        for (int e = 0; e < ED; e++) {
            q[e] = fmaf(a,  sqw[e*ZCH + c], q[e]);
            l[e] = fmaf(z2, slw[e*ZCH + c], l[e]);
        }
    }
    #pragma unroll
    for (int e = 0; e < ED; e++) { sq[pl][cg][e] = q[e]; sl[pl][cg][e] = l[e]; }
    __syncthreads();
    int eq = cg;
    float zz = 0.f;
    #pragma unroll
    for (int s = 0; s < 4; s++) {
        int e = eq * 4 + s;
        float qv = qb[e] + sq[pl][0][e] + sq[pl][1][e] + sq[pl][2][e] + sq[pl][3][e];
        g_z[(size_t)pos * ED + e] = qv;
        zz = fmaf(qv, qv, zz);
        float lv = lb[e] + sl[pl][0][e] + sl[pl][1][e] + sl[pl][2][e] + sl[pl][3][e];
        size_t oi = (size_t)b * ED * 1024 + (size_t)e * 1024 + rem;
        out_zl[oi] = lv;
        g_zl[oi]  = lv;
    }
    zz += __shfl_xor_sync(0xffffffffu, zz, 1);
    zz += __shfl_xor_sync(0xffffffffu, zz, 2);
    if (eq == 0) g_zz[pos] = zz;
}

// ---------------- pixelcnn 7x7 conv ----------------
__global__ void __launch_bounds__(256) k_pcn1(const float* __restrict__ w1, const float* __restrict__ b1) {
    __shared__ float img[8 * 1024];
    __shared__ float wt[ED * 49];
    int b = blockIdx.x >> 6, oc = blockIdx.x & 63;
    int tid = threadIdx.x;
    for (int i = tid; i < ED * 49; i += 256) wt[i] = w1[(size_t)oc * ED * 49 + i];
    int y0 = (tid >> 4) * 2, x0 = (tid & 15) * 2;
    float bias = b1[oc];
    float a00 = bias, a01 = bias, a10 = bias, a11 = bias;
    for (int half = 0; half < 2; half++) {
        __syncthreads();
        for (int i = tid; i < 8192; i += 256) img[i] = g_zl[(size_t)b * 16384 + half * 8192 + i];
        __syncthreads();
        for (int ic = 0; ic < 8; ic++) {
            const float* ib = img + ic * 1024;
            const float* wb = wt + (half * 8 + ic) * 49;
            float r[8][8];
            #pragma unroll
            for (int wy = 0; wy < 8; wy++) {
                int yy = y0 - 3 + wy;
                #pragma unroll
                for (int wx = 0; wx < 8; wx++) {
                    int xx = x0 - 3 + wx;
                    r[wy][wx] = (yy >= 0 && yy < 32 && xx >= 0 && xx < 32) ? ib[yy*32 + xx] : 0.f;
                }
            }
            #pragma unroll
            for (int ky = 0; ky < 7; ky++)
                #pragma unroll
                for (int kx = 0; kx < 7; kx++) {
                    float wv = wb[ky*7 + kx];
                    a00 = fmaf(r[ky  ][kx  ], wv, a00);
                    a01 = fmaf(r[ky  ][kx+1], wv, a01);
                    a10 = fmaf(r[ky+1][kx  ], wv, a10);
                    a11 = fmaf(r[ky+1][kx+1], wv, a11);
                }
        }
    }
    int p00 = y0*32 + x0;
    g_h[(size_t)(b*1024 + p00     ) * PCH + oc] = fmaxf(a00, 0.f);
    g_h[(size_t)(b*1024 + p00 + 1 ) * PCH + oc] = fmaxf(a01, 0.f);
    g_h[(size_t)(b*1024 + p00 + 32) * PCH + oc] = fmaxf(a10, 0.f);
    g_h[(size_t)(b*1024 + p00 + 33) * PCH + oc] = fmaxf(a11, 0.f);
}

// ---------------- mega-kernel device paths ----------------
#define SA_STR 132
#define SB_STR 132

// exact fp32 logits GEMM (R11 form)
__device__ void dev_fgemm(char* smem, int bx,
                          const float* __restrict__ W,
                          const float* __restrict__ bias,
                          float* __restrict__ C)
{
    float* sA = (float*)smem;                 // [32][132]
    float* sB = sA + 32 * SA_STR;             // [32][132]
    const int n0 = (bx & 127) * 128, m0 = (bx >> 7) * 128;
    const int nbt_idx = bx & 127;
    const int tid = threadIdx.x;
    const int tx = tid & 15, ty = tid >> 4;

    u64t acc2[4][8];
    #pragma unroll
    for (int i = 0; i < 4; i++)
        #pragma unroll
        for (int j = 0; j < 8; j++) acc2[i][j] = 0ull;

    #pragma unroll 1
    for (int kc = 0; kc < 2; kc++) {
        #pragma unroll
        for (int t = 0; t < 4; t++) {
            int e = tid + t * 256;
            int row = (e >> 2) & 127;
            int kq = (e >> 9) * 16 + (e & 3) * 4;
            float4 va = *(const float4*)(g_h + (size_t)(m0 + row) * PCH + kc * 32 + kq);
            sA[(kq+0)*SA_STR + row] = va.x; sA[(kq+1)*SA_STR + row] = va.y;
            sA[(kq+2)*SA_STR + row] = va.z; sA[(kq+3)*SA_STR + row] = va.w;
            float4 vb = *(const float4*)(W + (size_t)(n0 + row) * PCH + kc * 32 + kq);
            sB[(kq+0)*SB_STR + row] = vb.x; sB[(kq+1)*SB_STR + row] = vb.y;
            sB[(kq+2)*SB_STR + row] = vb.z; sB[(kq+3)*SB_STR + row] = vb.w;
        }
        __syncthreads();
        #pragma unroll 16
        for (int k = 0; k < 32; k++) {
            ulonglong2 a01 = *(const ulonglong2*)(sA + k * SA_STR + ty*8);
            ulonglong2 a23 = *(const ulonglong2*)(sA + k * SA_STR + ty*8 + 4);
            u64t a[4] = {a01.x, a01.y, a23.x, a23.y};
            float4 b0 = *(const float4*)(sB + k * SB_STR + tx*4);
            float4 b1 = *(const float4*)(sB + k * SB_STR + 64 + tx*4);
            u64t bv[8];
            bv[0] = dup2(b0.x); bv[1] = dup2(b0.y); bv[2] = dup2(b0.z); bv[3] = dup2(b0.w);
            bv[4] = dup2(b1.x); bv[5] = dup2(b1.y); bv[6] = dup2(b1.z); bv[7] = dup2(b1.w);
            #pragma unroll
            for (int i = 0; i < 4; i++)
                #pragma unroll
                for (int j = 0; j < 8; j++)
                    fma2(acc2[i][j], a[i], bv[j]);
        }
        __syncthreads();
    }

    float4 bb0 = *(const float4*)(bias + n0 + tx*4);
    float4 bb1 = *(const float4*)(bias + n0 + 64 + tx*4);
    float bb[8] = {bb0.x, bb0.y, bb0.z, bb0.w, bb1.x, bb1.y, bb1.z, bb1.w};

    float* sval = sA;
    int*   sidx = (int*)sB;
    #pragma unroll
    for (int i = 0; i < 4; i++) {
        int r0 = ty*8 + 2*i, r1 = r0 + 1;
        float v0[8], v1[8];
        #pragma unroll
        for (int j = 0; j < 8; j++) {
            float lo, hi; unpack2(lo, hi, acc2[i][j]);
            v0[j] = lo + bb[j]; v1[j] = hi + bb[j];
        }
        *(float4*)(C + (size_t)(m0 + r0) * NEMB + n0 + tx*4)      = make_float4(v0[0], v0[1], v0[2], v0[3]);
        *(float4*)(C + (size_t)(m0 + r0) * NEMB + n0 + 64 + tx*4) = make_float4(v0[4], v0[5], v0[6], v0[7]);
        *(float4*)(C + (size_t)(m0 + r1) * NEMB + n0 + tx*4)      = make_float4(v1[0], v1[1], v1[2], v1[3]);
        *(float4*)(C + (size_t)(m0 + r1) * NEMB + n0 + 64 + tx*4) = make_float4(v1[4], v1[5], v1[6], v1[7]);
        float best0 = v0[0], best1 = v1[0]; int bi0 = n0 + tx*4, bi1 = n0 + tx*4;
        #pragma unroll
        for (int j = 1; j < 8; j++) {
            int col = (j < 4) ? (n0 + tx*4 + j) : (n0 + 64 + tx*4 + j - 4);
            if (v0[j] > best0) { best0 = v0[j]; bi0 = col; }
            if (v1[j] > best1) { best1 = v1[j]; bi1 = col; }
        }
        sval[r0*16 + tx] = best0; sidx[r0*16 + tx] = bi0;
        sval[r1*16 + tx] = best1; sidx[r1*16 + tx] = bi1;
    }
    __syncthreads();
    if (tid < 128) {
        float bv = sval[tid*16]; int bi = sidx[tid*16];
        #pragma unroll
        for (int t = 1; t < 16; t++) {
            float v = sval[tid*16 + t]; int ii = sidx[tid*16 + t];
            if (v > bv || (v == bv && ii < bi)) { bv = v; bi = ii; }
        }
        g_pv[(size_t)(m0 + tid) * NBT + nbt_idx] = bv;
        g_pi[(size_t)(m0 + tid) * NBT + nbt_idx] = bi;
    }
}

// exact fp32 VQ distance GEMM (K=16)
__device__ void dev_vqgemm(char* smem, int bx, const float* __restrict__ Bm)
{
    float* sA = (float*)smem;
    float* sB = sA + 16 * SA_STR;
    const int n0 = (bx & 127) * 128, m0 = (bx >> 7) * 128;
    const int nbt_idx = bx & 127;
    const int tid = threadIdx.x;
    const int tx = tid & 15, ty = tid >> 4;

    u64t acc2[4][8];
    #pragma unroll
    for (int i = 0; i < 4; i++)
        #pragma unroll
        for (int j = 0; j < 8; j++) acc2[i][j] = 0ull;

    #pragma unroll
    for (int t = 0; t < 2; t++) {
        int e = tid + t * 256;
        int row = e >> 2, q = (e & 3) * 4;
        float4 va = *(const float4*)(g_z + (size_t)(m0 + row) * ED + q);
        sA[(q+0)*SA_STR + row] = va.x; sA[(q+1)*SA_STR + row] = va.y;
        sA[(q+2)*SA_STR + row] = va.z; sA[(q+3)*SA_STR + row] = va.w;
        float4 vb = *(const float4*)(Bm + (size_t)(n0 + row) * ED + q);
        sB[(q+0)*SB_STR + row] = vb.x; sB[(q+1)*SB_STR + row] = vb.y;
        sB[(q+2)*SB_STR + row] = vb.z; sB[(q+3)*SB_STR + row] = vb.w;
    }
    __syncthreads();
    #pragma unroll
    for (int k = 0; k < 16; k++) {
        ulonglong2 a01 = *(const ulonglong2*)(sA + k * SA_STR + ty*8);
        ulonglong2 a23 = *(const ulonglong2*)(sA + k * SA_STR + ty*8 + 4);
        u64t a[4] = {a01.x, a01.y, a23.x, a23.y};
        float4 b0 = *(const float4*)(sB + k * SB_STR + tx*4);
        float4 b1 = *(const float4*)(sB + k * SB_STR + 64 + tx*4);
        u64t bv[8];
        bv[0] = dup2(b0.x); bv[1] = dup2(b0.y); bv[2] = dup2(b0.z); bv[3] = dup2(b0.w);
        bv[4] = dup2(b1.x); bv[5] = dup2(b1.y); bv[6] = dup2(b1.z); bv[7] = dup2(b1.w);
        #pragma unroll
        for (int i = 0; i < 4; i++)
            #pragma unroll
            for (int j = 0; j < 8; j++)
                fma2(acc2[i][j], a[i], bv[j]);
    }
    __syncthreads();

    float4 nv0 = *(const float4*)(g_cnorm + n0 + tx*4);
    float4 nv1 = *(const float4*)(g_cnorm + n0 + 64 + tx*4);
    float nv[8] = {nv0.x, nv0.y, nv0.z, nv0.w, nv1.x, nv1.y, nv1.z, nv1.w};

    float* sval = sA;
    int*   sidx = (int*)sB;
    #pragma unroll
    for (int i = 0; i < 4; i++) {
        int r0 = ty*8 + 2*i, r1 = r0 + 1;
        float zz0 = g_zz[m0 + r0], zz1 = g_zz[m0 + r1];
        float best0 = 3.4e38f, best1 = 3.4e38f; int bi0 = 0, bi1 = 0;
        #pragma unroll
        for (int j = 0; j < 8; j++) {
            float lo, hi; unpack2(lo, hi, acc2[i][j]);
            int col = (j < 4) ? (n0 + tx*4 + j) : (n0 + 64 + tx*4 + j - 4);
            float d0 = zz0 + nv[j] - 2.f * lo;
            float d1 = zz1 + nv[j] - 2.f * hi;
            if (d0 < best0 || (d0 == best0 && col < bi0)) { best0 = d0; bi0 = col; }
            if (d1 < best1 || (d1 == best1 && col < bi1)) { best1 = d1; bi1 = col; }
        }
        sval[r0*16 + tx] = best0; sidx[r0*16 + tx] = bi0;
        sval[r1*16 + tx] = best1; sidx[r1*16 + tx] = bi1;
    }
    __syncthreads();
    if (tid < 128) {
        float bv = sval[tid*16]; int bi = sidx[tid*16];
        #pragma unroll
        for (int t = 1; t < 16; t++) {
            float v = sval[tid*16 + t]; int ii = sidx[tid*16 + t];
            if (v < bv || (v == bv && ii < bi)) { bv = v; bi = ii; }
        }
        g_pv2[(size_t)(m0 + tid) * NBT + nbt_idx] = bv;
        g_pi2[(size_t)(m0 + tid) * NBT + nbt_idx] = bi;
    }
}

// fuse conv 3x3 @64x64 (raw conv+bias into g_t)
__device__ void dev_fuseconv(char* smem, int bx,
                             const float* __restrict__ ff,
                             const float* __restrict__ fw,
                             const float* __restrict__ fb)
{
    float* slice = (float*)smem;
    float* swf = slice + 8192;
    int b = bx >> 6, oc = bx & 63;
    int tid = threadIdx.x;
    for (int i = tid; i < ZCH * 9; i += 256) swf[i] = fw[(size_t)oc * ZCH * 9 + i];
    int ty0 = (tid >> 4) * 4, tx0 = (tid & 15) * 4;
    float acc[4][4];
    float bb = fb[oc];
    #pragma unroll
    for (int i = 0; i < 4; i++)
        #pragma unroll
        for (int j = 0; j < 4; j++) acc[i][j] = bb;
    for (int icp = 0; icp < 32; icp++) {
        __syncthreads();
        for (int i = tid; i < 8192; i += 256)
            slice[i] = ff[(size_t)b * ZCH * 4096 + (size_t)icp * 8192 + i];
        __syncthreads();
        for (int s = 0; s < 2; s++) {
            const float* ib = slice + s * 4096;
            const float* wb = swf + (icp * 2 + s) * 9;
            float r[6][6];
            #pragma unroll
            for (int yy = 0; yy < 6; yy++)
                #pragma unroll
                for (int xx = 0; xx < 6; xx++) {
                    int Y = ty0 + yy - 1, X = tx0 + xx - 1;
                    r[yy][xx] = (Y >= 0 && Y < 64 && X >= 0 && X < 64) ? ib[Y*64 + X] : 0.f;
                }
            #pragma unroll
            for (int ky = 0; ky < 3; ky++)
                #pragma unroll
                for (int kx = 0; kx < 3; kx++) {
                    float wv = wb[ky*3 + kx];
                    #pragma unroll
                    for (int i = 0; i < 4; i++)
                        #pragma unroll
                        for (int j = 0; j < 4; j++)
                            acc[i][j] = fmaf(r[i+ky][j+kx], wv, acc[i][j]);
                }
        }
    }
    #pragma unroll
    for (int i = 0; i < 4; i++)
        #pragma unroll
        for (int j = 0; j < 4; j++) {
            int Y = ty0 + i, X = tx0 + j;
            g_t[(size_t)b * ZCH * 4096 + (size_t)oc * 4096 + Y*64 + X] = acc[i][j];
        }
}

// ---------------- mega: fgemm (0..4095) | vqgemm (4096..8191) | fuseconv (8192..8447 LAST) ----------------
#define MEGA_SMEM 35072
__global__ void __launch_bounds__(256, 2) k_mega(
    const float* __restrict__ W, const float* __restrict__ bias, float* __restrict__ C,
    const float* __restrict__ cb,
    const float* __restrict__ ff, const float* __restrict__ fw, const float* __restrict__ fb)
{
    __shared__ __align__(16) char smem[MEGA_SMEM];
    int bx = blockIdx.x;
    if (bx < 4096)           dev_fgemm(smem, bx, W, bias, C);
    else if (bx < 8192)      dev_vqgemm(smem, bx - 4096, cb);
    else                     dev_fuseconv(smem, bx - 8192, ff, fw, fb);
}

// ---------------- combined argreduce ----------------
__global__ void k_argboth(float* __restrict__ outf,
                          const float* __restrict__ cb,
                          float* __restrict__ out_zhq) {
    int blk = blockIdx.x;
    bool ismax = blk < NPOS;
    int row = ismax ? blk : blk - NPOS;
    int t = threadIdx.x;
    __shared__ float sv[128];
    __shared__ int   si[128];
    const float* pv = ismax ? g_pv : g_pv2;
    const int*   pi = ismax ? g_pi : g_pi2;
    sv[t] = pv[(size_t)row * NBT + t];
    si[t] = pi[(size_t)row * NBT + t];
    __syncthreads();
    for (int s = 64; s; s >>= 1) {
        if (t < s) {
            float v2 = sv[t+s]; int i2 = si[t+s];
            bool better = ismax ? (v2 > sv[t]) : (v2 < sv[t]);
            if (better || (v2 == sv[t] && i2 < si[t])) { sv[t] = v2; si[t] = i2; }
        }
        __syncthreads();
    }
    if (ismax) {
        if (t == 0) g_topidx[row] = si[0];
    } else {
        if (t == 0) { g_vqidx[row] = si[0]; outf[row] = (float)si[0]; }
        if (t < ED) {
            int b = row >> 10, rem = row & 1023;
            out_zhq[(size_t)b * ED * 1024 + (size_t)t * 1024 + rem] = cb[(size_t)si[0] * ED + t];
        }
    }
}

// ---------------- post-quant 1x1 ----------------
__global__ void __launch_bounds__(256) k_pq(const float* __restrict__ cb,
                                            const float* __restrict__ pqw,
                                            const float* __restrict__ pqb) {
    __shared__ float scode[64][17];
    __shared__ float spw[ZCH * ED];
    __shared__ float spb[ZCH];
    int tid = threadIdx.x;
    for (int i = tid; i < ZCH * ED; i += 256) spw[i] = pqw[i];
    if (tid < ZCH) spb[tid] = pqb[tid];
    {
        int e = tid & 15;
        #pragma unroll
        for (int it = 0; it < 4; it++) {
            int pos_l = (tid >> 4) + it * 16;
            int pos = blockIdx.x * 64 + pos_l;
            scode[pos_l][e] = cb[(size_t)g_topidx[pos] * ED + e];
        }
    }
    __syncthreads();
    int pl = tid >> 2, zg = tid & 3;
    int pos = blockIdx.x * 64 + pl;
    int b = pos >> 10, rem = pos & 1023;
    float code[ED];
    #pragma unroll
    for (int e = 0; e < ED; e++) code[e] = scode[pl][e];
    #pragma unroll
    for (int zz = 0; zz < 16; zz++) {
        int zc = zg * 16 + zz;
        float a = spb[zc];
        #pragma unroll
        for (int e = 0; e < ED; e++) a = fmaf(spw[zc*ED + e], code[e], a);
        g_dcin[(size_t)b * ZCH * 1024 + (size_t)zc * 1024 + rem] = a;
    }
}

// ---------------- dec1 3x3 ----------------
__global__ void __launch_bounds__(256) k_dec1(const float* __restrict__ w, const float* __restrict__ bias) {
    __shared__ float slice[8 * 1024];
    __shared__ float sw[ZCH * 9];
    int b = blockIdx.x >> 6, oc = blockIdx.x & 63;
    int tid = threadIdx.x;
    for (int i = tid; i < ZCH * 9; i += 256) sw[i] = w[(size_t)oc * ZCH * 9 + i];
    int y0 = (tid >> 4) * 2, x0 = (tid & 15) * 2;
    float bb = bias[oc];
    float a00 = bb, a01 = bb, a10 = bb, a11 = bb;
    for (int st = 0; st < 8; st++) {
        __syncthreads();
        for (int i = tid; i < 8192; i += 256)
            slice[i] = g_dcin[(size_t)b * 65536 + (size_t)st * 8192 + i];
        __syncthreads();
        for (int s = 0; s < 8; s++) {
            const float* ib = slice + s * 1024;
            const float* wb = sw + (st * 8 + s) * 9;
            float r[4][4];
            #pragma unroll
            for (int wy = 0; wy < 4; wy++) {
                int yy = y0 - 1 + wy;
                #pragma unroll
                for (int wx = 0; wx < 4; wx++) {
                    int xx = x0 - 1 + wx;
                    r[wy][wx] = (yy >= 0 && yy < 32 && xx >= 0 && xx < 32) ? ib[yy*32 + xx] : 0.f;
                }
            }
            #pragma unroll
            for (int ky = 0; ky < 3; ky++)
                #pragma unroll
                for (int kx = 0; kx < 3; kx++) {
                    float wv = wb[ky*3 + kx];
                    a00 = fmaf(r[ky  ][kx  ], wv, a00);
                    a01 = fmaf(r[ky  ][kx+1], wv, a01);
                    a10 = fmaf(r[ky+1][kx  ], wv, a10);
                    a11 = fmaf(r[ky+1][kx+1], wv, a11);
                }
        }
    }
    size_t ob = (size_t)b * 65536 + (size_t)oc * 1024;
    int p00 = y0*32 + x0;
    g_d0[ob + p00     ] = fmaxf(a00, 0.f);
    g_d0[ob + p00 + 1 ] = fmaxf(a01, 0.f);
    g_d0[ob + p00 + 32] = fmaxf(a10, 0.f);
    g_d0[ob + p00 + 33] = fmaxf(a11, 0.f);
}

// ---------------- fuse combine ----------------
__global__ void __launch_bounds__(256) k_fuse2(const void* __restrict__ wscalar) {
    int o = blockIdx.x * 256 + threadIdx.x;
    float wf = get_w(wscalar);
    int X = o & 63, Y = (o >> 6) & 63;
    int oc = (o >> 12) & 63, b = o >> 18;
    float conv = g_t[o];
    float d0 = g_d0[(size_t)b * 65536 + (size_t)oc * 1024 + (Y >> 1) * 32 + (X >> 1)];
    g_t[o] = fmaxf(d0 + wf * conv, 0.f);
}

// ---------------- dec2 ----------------
__global__ void __launch_bounds__(256) k_dec2(const float* __restrict__ w2,
                                              const float* __restrict__ b2,
                                              float* __restrict__ out_dec) {
    __shared__ float sw[ZCH * 9];
    int tid = threadIdx.x;
    for (int i = tid; i < ZCH * 9; i += 256) sw[i] = w2[i];
    __syncthreads();
    int b = blockIdx.x >> 6;
    int Y = (blockIdx.x & 63) * 2 + (tid >> 7);
    int X = tid & 127;
    float acc = b2[0];
    const float* tb = g_t + (size_t)b * ZCH * 4096;
    #pragma unroll 2
    for (int c = 0; c < ZCH; c++) {
        const float* ts = tb + (size_t)c * 4096;
        const float* wc = sw + c * 9;
        #pragma unroll
        for (int ky = 0; ky < 3; ky++) {
            int Yt = Y + ky - 1;
            if (Yt < 0 || Yt > 127) continue;
            int tr = (Yt >> 1) * 64;
            #pragma unroll
            for (int kx = 0; kx < 3; kx++) {
                int Xt = X + kx - 1;
                if (Xt < 0 || Xt > 127) continue;
                acc = fmaf(__ldg(&ts[tr + (Xt >> 1)]), wc[ky*3 + kx], acc);
            }
        }
    }
    out_dec[(size_t)b * 16384 + Y * 128 + X] = acc;
}

extern "C" void kernel_launch(void* const* d_in, const int* in_sizes, int n_in,
                              void* d_out, int out_size) {
    const float* z_t      = (const float*)d_in[0];
    const float* z_l_pre  = (const float*)d_in[1];
    const float* fuse_feat= (const float*)d_in[2];
    const void*  wptr     = d_in[3];
    const float* quant_w  = (const float*)d_in[4];
    const float* quant_b  = (const float*)d_in[5];
    const float* codebook = (const float*)d_in[6];
    const float* lrq_w    = (const float*)d_in[7];
    const float* lrq_b    = (const float*)d_in[8];
    const float* pcn_w1   = (const float*)d_in[9];
    const float* pcn_b1   = (const float*)d_in[10];
    const float* pcn_w2   = (const float*)d_in[11];
    const float* pcn_b2   = (const float*)d_in[12];
    const float* pq_w     = (const float*)d_in[13];
    const float* pq_b     = (const float*)d_in[14];
    const float* dec_w1   = (const float*)d_in[15];
    const float* dec_b1   = (const float*)d_in[16];
    const float* fuse_w   = (const float*)d_in[17];
    const float* fuse_b   = (const float*)d_in[18];
    const float* dec_w2   = (const float*)d_in[19];
    const float* dec_b2   = (const float*)d_in[20];

    float* out = (float*)d_out;
    float* out_logits = out;
    float* out_zl     = out_logits + (size_t)NPOS * NEMB;
    float* out_tgt    = out_zl + (size_t)BATCH * ED * 1024;
    float* out_zhq    = out_tgt + NPOS;
    float* out_dec    = out_zhq + (size_t)BATCH * ED * 1024;

    k_cnorm<<<NEMB/256, 256>>>(codebook);                                                 // 0
    k_quant_lrq<<<NPOS/64, 256>>>(z_t, z_l_pre, quant_w, quant_b, lrq_w, lrq_b, out_zl);  // 1
    k_pcn1<<<BATCH*PCH, 256>>>(pcn_w1, pcn_b1);                                           // 2
    k_mega<<<4096 + 4096 + 256, 256>>>(pcn_w2, pcn_b2, out_logits,                        // 3
                                       codebook, fuse_feat, fuse_w, fuse_b);
    k_argboth<<<2*NPOS, 128>>>(out_tgt, codebook, out_zhq);                               // 4
    k_pq<<<NPOS/64, 256>>>(codebook, pq_w, pq_b);                                         // 5
    k_dec1<<<BATCH*ZCH, 256>>>(dec_w1, dec_b1);                                           // 6
    k_fuse2<<<(BATCH*ZCH*4096)/256, 256>>>(wptr);                                         // 7
    k_dec2<<<BATCH*64, 256>>>(dec_w2, dec_b2, out_dec);                                   // 8
}

// round 16
// speedup vs baseline: 1.0361x; 1.0361x over previous
#include <cuda_runtime.h>
#include <cstdint>
#include <cstddef>

#define BATCH 4
#define ZCH 64
#define ED 16
#define NEMB 16384
#define PCH 64
#define FRES 32
#define NPOS (BATCH*FRES*FRES)
#define NBT (NEMB/128)

// ---------------- scratch ----------------
__device__ float g_z[NPOS*ED];
__device__ float g_zz[NPOS];
__device__ float g_cnorm[NEMB];
__device__ float g_zl[BATCH*ED*FRES*FRES];
__device__ float g_h[NPOS*PCH];
__device__ float g_pv[(size_t)NPOS*NBT];
__device__ int   g_pi[(size_t)NPOS*NBT];
__device__ float g_pv2[(size_t)NPOS*NBT];
__device__ int   g_pi2[(size_t)NPOS*NBT];
__device__ int   g_vqidx[NPOS];
__device__ int   g_topidx[NPOS];
__device__ float g_dcin[BATCH*ZCH*FRES*FRES];
__device__ float g_t[BATCH*ZCH*64*64];

typedef unsigned long long u64t;

__device__ __forceinline__ void fma2(u64t& d, u64t a, u64t b) {
    asm("fma.rn.f32x2 %0, %1, %2, %0;" : "+l"(d) : "l"(a), "l"(b));
}
__device__ __forceinline__ u64t dup2(float x) {
    u64t p;
    asm("mov.b64 %0, {%1, %1};" : "=l"(p) : "f"(x));
    return p;
}
__device__ __forceinline__ void unpack2(float& lo, float& hi, u64t p) {
    asm("mov.b64 {%0, %1}, %2;" : "=f"(lo), "=f"(hi) : "l"(p));
}

__device__ __forceinline__ float get_w(const void* wp) {
    int i = *(const int*)wp;
    float f = __int_as_float(i);
    float af = fabsf(f);
    if (af < 1e-20f) return (float)i;
    if (i > -100000000 && i < 100000000) return (float)i;
    return f;
}

// ---------------- quant+lrq (blocks 0..63) + cnorm (blocks 64..127) ----------------
__global__ void __launch_bounds__(256) k_prep(
    const float* __restrict__ zt, const float* __restrict__ zlp,
    const float* __restrict__ qw, const float* __restrict__ qb,
    const float* __restrict__ lw, const float* __restrict__ lb,
    const float* __restrict__ cb,
    float* __restrict__ out_zl)
{
    if (blockIdx.x >= 64) {
        int n = (blockIdx.x - 64) * 256 + threadIdx.x;
        const float* r = cb + (size_t)n * ED;
        float s = 0.f;
        #pragma unroll
        for (int e = 0; e < ED; e++) s += r[e] * r[e];
        g_cnorm[n] = s;
        return;
    }
    __shared__ float sqw[ED*ZCH];
    __shared__ float slw[ED*ZCH];
    __shared__ float sq[64][4][17];
    __shared__ float sl[64][4][17];
    int tid = threadIdx.x;
    for (int i = tid; i < ED*ZCH; i += 256) { sqw[i] = qw[i]; slw[i] = lw[i]; }
    int pl = tid >> 2, cg = tid & 3;
    int pos = blockIdx.x * 64 + pl;
    int b = pos >> 10, rem = pos & 1023;
    size_t base = (size_t)b * ZCH * 1024 + rem;
    float q[ED], l[ED];
    #pragma unroll
    for (int e = 0; e < ED; e++) { q[e] = 0.f; l[e] = 0.f; }
    __syncthreads();
    #pragma unroll
    for (int cc = 0; cc < 16; cc++) {
        int c = cg * 16 + cc;
        float a  = zt[base + (size_t)c * 1024];
        float z2 = zlp[base + (size_t)c * 1024];
        #pragma unroll
        for (int e = 0; e < ED; e++) {
            q[e] = fmaf(a,  sqw[e*ZCH + c], q[e]);
            l[e] = fmaf(z2, slw[e*ZCH + c], l[e]);
        }
    }
    #pragma unroll
    for (int e = 0; e < ED; e++) { sq[pl][cg][e] = q[e]; sl[pl][cg][e] = l[e]; }
    __syncthreads();
    int eq = cg;
    float zz = 0.f;
    #pragma unroll
    for (int s = 0; s < 4; s++) {
        int e = eq * 4 + s;
        float qv = qb[e] + sq[pl][0][e] + sq[pl][1][e] + sq[pl][2][e] + sq[pl][3][e];
        g_z[(size_t)pos * ED + e] = qv;
        zz = fmaf(qv, qv, zz);
        float lv = lb[e] + sl[pl][0][e] + sl[pl][1][e] + sl[pl][2][e] + sl[pl][3][e];
        size_t oi = (size_t)b * ED * 1024 + (size_t)e * 1024 + rem;
        out_zl[oi] = lv;
        g_zl[oi]  = lv;
    }
    zz += __shfl_xor_sync(0xffffffffu, zz, 1);
    zz += __shfl_xor_sync(0xffffffffu, zz, 2);
    if (eq == 0) g_zz[pos] = zz;
}

// ---------------- pixelcnn 7x7 conv ----------------
__global__ void __launch_bounds__(256) k_pcn1(const float* __restrict__ w1, const float* __restrict__ b1) {
    __shared__ float img[8 * 1024];
    __shared__ float wt[ED * 49];
    int b = blockIdx.x >> 6, oc = blockIdx.x & 63;
    int tid = threadIdx.x;
    for (int i = tid; i < ED * 49; i += 256) wt[i] = w1[(size_t)oc * ED * 49 + i];
    int y0 = (tid >> 4) * 2, x0 = (tid & 15) * 2;
    float bias = b1[oc];
    float a00 = bias, a01 = bias, a10 = bias, a11 = bias;
    for (int half = 0; half < 2; half++) {
        __syncthreads();
        for (int i = tid; i < 8192; i += 256) img[i] = g_zl[(size_t)b * 16384 + half * 8192 + i];
        __syncthreads();
        for (int ic = 0; ic < 8; ic++) {
            const float* ib = img + ic * 1024;
            const float* wb = wt + (half * 8 + ic) * 49;
            float r[8][8];
            #pragma unroll
            for (int wy = 0; wy < 8; wy++) {
                int yy = y0 - 3 + wy;
                #pragma unroll
                for (int wx = 0; wx < 8; wx++) {
                    int xx = x0 - 3 + wx;
                    r[wy][wx] = (yy >= 0 && yy < 32 && xx >= 0 && xx < 32) ? ib[yy*32 + xx] : 0.f;
                }
            }
            #pragma unroll
            for (int ky = 0; ky < 7; ky++)
                #pragma unroll
                for (int kx = 0; kx < 7; kx++) {
                    float wv = wb[ky*7 + kx];
                    a00 = fmaf(r[ky  ][kx  ], wv, a00);
                    a01 = fmaf(r[ky  ][kx+1], wv, a01);
                    a10 = fmaf(r[ky+1][kx  ], wv, a10);
                    a11 = fmaf(r[ky+1][kx+1], wv, a11);
                }
        }
    }
    int p00 = y0*32 + x0;
    g_h[(size_t)(b*1024 + p00     ) * PCH + oc] = fmaxf(a00, 0.f);
    g_h[(size_t)(b*1024 + p00 + 1 ) * PCH + oc] = fmaxf(a01, 0.f);
    g_h[(size_t)(b*1024 + p00 + 32) * PCH + oc] = fmaxf(a10, 0.f);
    g_h[(size_t)(b*1024 + p00 + 33) * PCH + oc] = fmaxf(a11, 0.f);
}

// ---------------- mega-kernel device paths ----------------
#define SA_STR 132
#define SB_STR 132

__device__ void dev_fgemm(char* smem, int bx,
                          const float* __restrict__ W,
                          const float* __restrict__ bias,
                          float* __restrict__ C)
{
    float* sA = (float*)smem;
    float* sB = sA + 32 * SA_STR;
    const int n0 = (bx & 127) * 128, m0 = (bx >> 7) * 128;
    const int nbt_idx = bx & 127;
    const int tid = threadIdx.x;
    const int tx = tid & 15, ty = tid >> 4;

    u64t acc2[4][8];
    #pragma unroll
    for (int i = 0; i < 4; i++)
        #pragma unroll
        for (int j = 0; j < 8; j++) acc2[i][j] = 0ull;

    #pragma unroll 1
    for (int kc = 0; kc < 2; kc++) {
        #pragma unroll
        for (int t = 0; t < 4; t++) {
            int e = tid + t * 256;
            int row = (e >> 2) & 127;
            int kq = (e >> 9) * 16 + (e & 3) * 4;
            float4 va = *(const float4*)(g_h + (size_t)(m0 + row) * PCH + kc * 32 + kq);
            sA[(kq+0)*SA_STR + row] = va.x; sA[(kq+1)*SA_STR + row] = va.y;
            sA[(kq+2)*SA_STR + row] = va.z; sA[(kq+3)*SA_STR + row] = va.w;
            float4 vb = *(const float4*)(W + (size_t)(n0 + row) * PCH + kc * 32 + kq);
            sB[(kq+0)*SB_STR + row] = vb.x; sB[(kq+1)*SB_STR + row] = vb.y;
            sB[(kq+2)*SB_STR + row] = vb.z; sB[(kq+3)*SB_STR + row] = vb.w;
        }
        __syncthreads();
        #pragma unroll 16
        for (int k = 0; k < 32; k++) {
            ulonglong2 a01 = *(const ulonglong2*)(sA + k * SA_STR + ty*8);
            ulonglong2 a23 = *(const ulonglong2*)(sA + k * SA_STR + ty*8 + 4);
            u64t a[4] = {a01.x, a01.y, a23.x, a23.y};
            float4 b0 = *(const float4*)(sB + k * SB_STR + tx*4);
            float4 b1 = *(const float4*)(sB + k * SB_STR + 64 + tx*4);
            u64t bv[8];
            bv[0] = dup2(b0.x); bv[1] = dup2(b0.y); bv[2] = dup2(b0.z); bv[3] = dup2(b0.w);
            bv[4] = dup2(b1.x); bv[5] = dup2(b1.y); bv[6] = dup2(b1.z); bv[7] = dup2(b1.w);
            #pragma unroll
            for (int i = 0; i < 4; i++)
                #pragma unroll
                for (int j = 0; j < 8; j++)
                    fma2(acc2[i][j], a[i], bv[j]);
        }
        __syncthreads();
    }

    float4 bb0 = *(const float4*)(bias + n0 + tx*4);
    float4 bb1 = *(const float4*)(bias + n0 + 64 + tx*4);
    float bb[8] = {bb0.x, bb0.y, bb0.z, bb0.w, bb1.x, bb1.y, bb1.z, bb1.w};

    float* sval = sA;
    int*   sidx = (int*)sB;
    #pragma unroll
    for (int i = 0; i < 4; i++) {
        int r0 = ty*8 + 2*i, r1 = r0 + 1;
        float v0[8], v1[8];
        #pragma unroll
        for (int j = 0; j < 8; j++) {
            float lo, hi; unpack2(lo, hi, acc2[i][j]);
            v0[j] = lo + bb[j]; v1[j] = hi + bb[j];
        }
        *(float4*)(C + (size_t)(m0 + r0) * NEMB + n0 + tx*4)      = make_float4(v0[0], v0[1], v0[2], v0[3]);
        *(float4*)(C + (size_t)(m0 + r0) * NEMB + n0 + 64 + tx*4) = make_float4(v0[4], v0[5], v0[6], v0[7]);
        *(float4*)(C + (size_t)(m0 + r1) * NEMB + n0 + tx*4)      = make_float4(v1[0], v1[1], v1[2], v1[3]);
        *(float4*)(C + (size_t)(m0 + r1) * NEMB + n0 + 64 + tx*4) = make_float4(v1[4], v1[5], v1[6], v1[7]);
        float best0 = v0[0], best1 = v1[0]; int bi0 = n0 + tx*4, bi1 = n0 + tx*4;
        #pragma unroll
        for (int j = 1; j < 8; j++) {
            int col = (j < 4) ? (n0 + tx*4 + j) : (n0 + 64 + tx*4 + j - 4);
            if (v0[j] > best0) { best0 = v0[j]; bi0 = col; }
            if (v1[j] > best1) { best1 = v1[j]; bi1 = col; }
        }
        sval[r0*16 + tx] = best0; sidx[r0*16 + tx] = bi0;
        sval[r1*16 + tx] = best1; sidx[r1*16 + tx] = bi1;
    }
    __syncthreads();
    if (tid < 128) {
        float bv = sval[tid*16]; int bi = sidx[tid*16];
        #pragma unroll
        for (int t = 1; t < 16; t++) {
            float v = sval[tid*16 + t]; int ii = sidx[tid*16 + t];
            if (v > bv || (v == bv && ii < bi)) { bv = v; bi = ii; }
        }
        g_pv[(size_t)(m0 + tid) * NBT + nbt_idx] = bv;
        g_pi[(size_t)(m0 + tid) * NBT + nbt_idx] = bi;
    }
}

__device__ void dev_vqgemm(char* smem, int bx, const float* __restrict__ Bm)
{
    float* sA = (float*)smem;
    float* sB = sA + 16 * SA_STR;
    const int n0 = (bx & 127) * 128, m0 = (bx >> 7) * 128;
    const int nbt_idx = bx & 127;
    const int tid = threadIdx.x;
    const int tx = tid & 15, ty = tid >> 4;

    u64t acc2[4][8];
    #pragma unroll
    for (int i = 0; i < 4; i++)
        #pragma unroll
        for (int j = 0; j < 8; j++) acc2[i][j] = 0ull;

    #pragma unroll
    for (int t = 0; t < 2; t++) {
        int e = tid + t * 256;
        int row = e >> 2, q = (e & 3) * 4;
        float4 va = *(const float4*)(g_z + (size_t)(m0 + row) * ED + q);
        sA[(q+0)*SA_STR + row] = va.x; sA[(q+1)*SA_STR + row] = va.y;
        sA[(q+2)*SA_STR + row] = va.z; sA[(q+3)*SA_STR + row] = va.w;
        float4 vb = *(const float4*)(Bm + (size_t)(n0 + row) * ED + q);
        sB[(q+0)*SB_STR + row] = vb.x; sB[(q+1)*SB_STR + row] = vb.y;
        sB[(q+2)*SB_STR + row] = vb.z; sB[(q+3)*SB_STR + row] = vb.w;
    }
    __syncthreads();
    #pragma unroll
    for (int k = 0; k < 16; k++) {
        ulonglong2 a01 = *(const ulonglong2*)(sA + k * SA_STR + ty*8);
        ulonglong2 a23 = *(const ulonglong2*)(sA + k * SA_STR + ty*8 + 4);
        u64t a[4] = {a01.x, a01.y, a23.x, a23.y};
        float4 b0 = *(const float4*)(sB + k * SB_STR + tx*4);
        float4 b1 = *(const float4*)(sB + k * SB_STR + 64 + tx*4);
        u64t bv[8];
        bv[0] = dup2(b0.x); bv[1] = dup2(b0.y); bv[2] = dup2(b0.z); bv[3] = dup2(b0.w);
        bv[4] = dup2(b1.x); bv[5] = dup2(b1.y); bv[6] = dup2(b1.z); bv[7] = dup2(b1.w);
        #pragma unroll
        for (int i = 0; i < 4; i++)
            #pragma unroll
            for (int j = 0; j < 8; j++)
                fma2(acc2[i][j], a[i], bv[j]);
    }
    __syncthreads();

    float4 nv0 = *(const float4*)(g_cnorm + n0 + tx*4);
    float4 nv1 = *(const float4*)(g_cnorm + n0 + 64 + tx*4);
    float nv[8] = {nv0.x, nv0.y, nv0.z, nv0.w, nv1.x, nv1.y, nv1.z, nv1.w};

    float* sval = sA;
    int*   sidx = (int*)sB;
    #pragma unroll
    for (int i = 0; i < 4; i++) {
        int r0 = ty*8 + 2*i, r1 = r0 + 1;
        float zz0 = g_zz[m0 + r0], zz1 = g_zz[m0 + r1];
        float best0 = 3.4e38f, best1 = 3.4e38f; int bi0 = 0, bi1 = 0;
        #pragma unroll
        for (int j = 0; j < 8; j++) {
            float lo, hi; unpack2(lo, hi, acc2[i][j]);
            int col = (j < 4) ? (n0 + tx*4 + j) : (n0 + 64 + tx*4 + j - 4);
            float d0 = zz0 + nv[j] - 2.f * lo;
            float d1 = zz1 + nv[j] - 2.f * hi;
            if (d0 < best0 || (d0 == best0 && col < bi0)) { best0 = d0; bi0 = col; }
            if (d1 < best1 || (d1 == best1 && col < bi1)) { best1 = d1; bi1 = col; }
        }
        sval[r0*16 + tx] = best0; sidx[r0*16 + tx] = bi0;
        sval[r1*16 + tx] = best1; sidx[r1*16 + tx] = bi1;
    }
    __syncthreads();
    if (tid < 128) {
        float bv = sval[tid*16]; int bi = sidx[tid*16];
        #pragma unroll
        for (int t = 1; t < 16; t++) {
            float v = sval[tid*16 + t]; int ii = sidx[tid*16 + t];
            if (v < bv || (v == bv && ii < bi)) { bv = v; bi = ii; }
        }
        g_pv2[(size_t)(m0 + tid) * NBT + nbt_idx] = bv;
        g_pi2[(size_t)(m0 + tid) * NBT + nbt_idx] = bi;
    }
}

__device__ void dev_fuseconv(char* smem, int bx,
                             const float* __restrict__ ff,
                             const float* __restrict__ fw,
                             const float* __restrict__ fb)
{
    float* slice = (float*)smem;
    float* swf = slice + 8192;
    int b = bx >> 6, oc = bx & 63;
    int tid = threadIdx.x;
    for (int i = tid; i < ZCH * 9; i += 256) swf[i] = fw[(size_t)oc * ZCH * 9 + i];
    int ty0 = (tid >> 4) * 4, tx0 = (tid & 15) * 4;
    float acc[4][4];
    float bb = fb[oc];
    #pragma unroll
    for (int i = 0; i < 4; i++)
        #pragma unroll
        for (int j = 0; j < 4; j++) acc[i][j] = bb;
    for (int icp = 0; icp < 32; icp++) {
        __syncthreads();
        for (int i = tid; i < 8192; i += 256)
            slice[i] = ff[(size_t)b * ZCH * 4096 + (size_t)icp * 8192 + i];
        __syncthreads();
        for (int s = 0; s < 2; s++) {
            const float* ib = slice + s * 4096;
            const float* wb = swf + (icp * 2 + s) * 9;
            float r[6][6];
            #pragma unroll
            for (int yy = 0; yy < 6; yy++)
                #pragma unroll
                for (int xx = 0; xx < 6; xx++) {
                    int Y = ty0 + yy - 1, X = tx0 + xx - 1;
                    r[yy][xx] = (Y >= 0 && Y < 64 && X >= 0 && X < 64) ? ib[Y*64 + X] : 0.f;
                }
            #pragma unroll
            for (int ky = 0; ky < 3; ky++)
                #pragma unroll
                for (int kx = 0; kx < 3; kx++) {
                    float wv = wb[ky*3 + kx];
                    #pragma unroll
                    for (int i = 0; i < 4; i++)
                        #pragma unroll
                        for (int j = 0; j < 4; j++)
                            acc[i][j] = fmaf(r[i+ky][j+kx], wv, acc[i][j]);
                }
        }
    }
    #pragma unroll
    for (int i = 0; i < 4; i++)
        #pragma unroll
        for (int j = 0; j < 4; j++) {
            int Y = ty0 + i, X = tx0 + j;
            g_t[(size_t)b * ZCH * 4096 + (size_t)oc * 4096 + Y*64 + X] = acc[i][j];
        }
}

// ---------------- mega (R14 ordering: fuseconv first — measured best) ----------------
#define MEGA_SMEM 35072
__global__ void __launch_bounds__(256, 2) k_mega(
    const float* __restrict__ W, const float* __restrict__ bias, float* __restrict__ C,
    const float* __restrict__ cb,
    const float* __restrict__ ff, const float* __restrict__ fw, const float* __restrict__ fb)
{
    __shared__ __align__(16) char smem[MEGA_SMEM];
    int bx = blockIdx.x;
    if (bx < 256)            dev_fuseconv(smem, bx, ff, fw, fb);
    else if (bx < 256+4096)  dev_fgemm(smem, bx - 256, W, bias, C);
    else                     dev_vqgemm(smem, bx - (256+4096), cb);
}

// ---------------- combined argreduce ----------------
__global__ void k_argboth(float* __restrict__ outf,
                          const float* __restrict__ cb,
                          float* __restrict__ out_zhq) {
    int blk = blockIdx.x;
    bool ismax = blk < NPOS;
    int row = ismax ? blk : blk - NPOS;
    int t = threadIdx.x;
    __shared__ float sv[128];
    __shared__ int   si[128];
    const float* pv = ismax ? g_pv : g_pv2;
    const int*   pi = ismax ? g_pi : g_pi2;
    sv[t] = pv[(size_t)row * NBT + t];
    si[t] = pi[(size_t)row * NBT + t];
    __syncthreads();
    for (int s = 64; s; s >>= 1) {
        if (t < s) {
            float v2 = sv[t+s]; int i2 = si[t+s];
            bool better = ismax ? (v2 > sv[t]) : (v2 < sv[t]);
            if (better || (v2 == sv[t] && i2 < si[t])) { sv[t] = v2; si[t] = i2; }
        }
        __syncthreads();
    }
    if (ismax) {
        if (t == 0) g_topidx[row] = si[0];
    } else {
        if (t == 0) { g_vqidx[row] = si[0]; outf[row] = (float)si[0]; }
        if (t < ED) {
            int b = row >> 10, rem = row & 1023;
            out_zhq[(size_t)b * ED * 1024 + (size_t)t * 1024 + rem] = cb[(size_t)si[0] * ED + t];
        }
    }
}

// ---------------- post-quant 1x1 ----------------
__global__ void __launch_bounds__(256) k_pq(const float* __restrict__ cb,
                                            const float* __restrict__ pqw,
                                            const float* __restrict__ pqb) {
    __shared__ float scode[64][17];
    __shared__ float spw[ZCH * ED];
    __shared__ float spb[ZCH];
    int tid = threadIdx.x;
    for (int i = tid; i < ZCH * ED; i += 256) spw[i] = pqw[i];
    if (tid < ZCH) spb[tid] = pqb[tid];
    {
        int e = tid & 15;
        #pragma unroll
        for (int it = 0; it < 4; it++) {
            int pos_l = (tid >> 4) + it * 16;
            int pos = blockIdx.x * 64 + pos_l;
            scode[pos_l][e] = cb[(size_t)g_topidx[pos] * ED + e];
        }
    }
    __syncthreads();
    int pl = tid >> 2, zg = tid & 3;
    int pos = blockIdx.x * 64 + pl;
    int b = pos >> 10, rem = pos & 1023;
    float code[ED];
    #pragma unroll
    for (int e = 0; e < ED; e++) code[e] = scode[pl][e];
    #pragma unroll
    for (int zz = 0; zz < 16; zz++) {
        int zc = zg * 16 + zz;
        float a = spb[zc];
        #pragma unroll
        for (int e = 0; e < ED; e++) a = fmaf(spw[zc*ED + e], code[e], a);
        g_dcin[(size_t)b * ZCH * 1024 + (size_t)zc * 1024 + rem] = a;
    }
}

// ---------------- dec1 3x3 + fused up2/fuse-combine epilogue ----------------
// computes d0 = relu(conv3x3(g_dcin)), then directly g_t = relu(up2(d0) + w*g_t)
__global__ void __launch_bounds__(256) k_dec1(const float* __restrict__ w,
                                              const float* __restrict__ bias,
                                              const void* __restrict__ wscalar) {
    __shared__ float slice[8 * 1024];
    __shared__ float sw[ZCH * 9];
    int b = blockIdx.x >> 6, oc = blockIdx.x & 63;
    int tid = threadIdx.x;
    for (int i = tid; i < ZCH * 9; i += 256) sw[i] = w[(size_t)oc * ZCH * 9 + i];
    int y0 = (tid >> 4) * 2, x0 = (tid & 15) * 2;
    float bb = bias[oc];
    float a00 = bb, a01 = bb, a10 = bb, a11 = bb;
    for (int st = 0; st < 8; st++) {
        __syncthreads();
        for (int i = tid; i < 8192; i += 256)
            slice[i] = g_dcin[(size_t)b * 65536 + (size_t)st * 8192 + i];
        __syncthreads();
        for (int s = 0; s < 8; s++) {
            const float* ib = slice + s * 1024;
            const float* wb = sw + (st * 8 + s) * 9;
            float r[4][4];
            #pragma unroll
            for (int wy = 0; wy < 4; wy++) {
                int yy = y0 - 1 + wy;
                #pragma unroll
                for (int wx = 0; wx < 4; wx++) {
                    int xx = x0 - 1 + wx;
                    r[wy][wx] = (yy >= 0 && yy < 32 && xx >= 0 && xx < 32) ? ib[yy*32 + xx] : 0.f;
                }
            }
            #pragma unroll
            for (int ky = 0; ky < 3; ky++)
                #pragma unroll
                for (int kx = 0; kx < 3; kx++) {
                    float wv = wb[ky*3 + kx];
                    a00 = fmaf(r[ky  ][kx  ], wv, a00);
                    a01 = fmaf(r[ky  ][kx+1], wv, a01);
                    a10 = fmaf(r[ky+1][kx  ], wv, a10);
                    a11 = fmaf(r[ky+1][kx+1], wv, a11);
                }
        }
    }
    // epilogue: relu, then 2x upsample + fuse combine directly into g_t
    float d00 = fmaxf(a00, 0.f), d01 = fmaxf(a01, 0.f);
    float d10 = fmaxf(a10, 0.f), d11 = fmaxf(a11, 0.f);
    float wf = get_w(wscalar);
    float* tb = g_t + (size_t)b * ZCH * 4096 + (size_t)oc * 4096;
    int Y0 = y0 * 2, X0 = x0 * 2;     // 4x4 patch at (Y0, X0), X0 multiple of 4
    #pragma unroll
    for (int r = 0; r < 4; r++) {
        float dA = (r < 2) ? d00 : d10;
        float dB = (r < 2) ? d01 : d11;
        float4* tp = (float4*)(tb + (Y0 + r) * 64 + X0);
        float4 cv = *tp;
        float4 ov;
        ov.x = fmaxf(dA + wf * cv.x, 0.f);
        ov.y = fmaxf(dA + wf * cv.y, 0.f);
        ov.z = fmaxf(dB + wf * cv.z, 0.f);
        ov.w = fmaxf(dB + wf * cv.w, 0.f);
        *tp = ov;
    }
}

// ---------------- dec2 ----------------
__global__ void __launch_bounds__(256) k_dec2(const float* __restrict__ w2,
                                              const float* __restrict__ b2,
                                              float* __restrict__ out_dec) {
    __shared__ float sw[ZCH * 9];
    int tid = threadIdx.x;
    for (int i = tid; i < ZCH * 9; i += 256) sw[i] = w2[i];
    __syncthreads();
    int b = blockIdx.x >> 6;
    int Y = (blockIdx.x & 63) * 2 + (tid >> 7);
    int X = tid & 127;
    float acc = b2[0];
    const float* tb = g_t + (size_t)b * ZCH * 4096;
    #pragma unroll 2
    for (int c = 0; c < ZCH; c++) {
        const float* ts = tb + (size_t)c * 4096;
        const float* wc = sw + c * 9;
        #pragma unroll
        for (int ky = 0; ky < 3; ky++) {
            int Yt = Y + ky - 1;
            if (Yt < 0 || Yt > 127) continue;
            int tr = (Yt >> 1) * 64;
            #pragma unroll
            for (int kx = 0; kx < 3; kx++) {
                int Xt = X + kx - 1;
                if (Xt < 0 || Xt > 127) continue;
                acc = fmaf(__ldg(&ts[tr + (Xt >> 1)]), wc[ky*3 + kx], acc);
            }
        }
    }
    out_dec[(size_t)b * 16384 + Y * 128 + X] = acc;
}

extern "C" void kernel_launch(void* const* d_in, const int* in_sizes, int n_in,
                              void* d_out, int out_size) {
    const float* z_t      = (const float*)d_in[0];
    const float* z_l_pre  = (const float*)d_in[1];
    const float* fuse_feat= (const float*)d_in[2];
    const void*  wptr     = d_in[3];
    const float* quant_w  = (const float*)d_in[4];
    const float* quant_b  = (const float*)d_in[5];
    const float* codebook = (const float*)d_in[6];
    const float* lrq_w    = (const float*)d_in[7];
    const float* lrq_b    = (const float*)d_in[8];
    const float* pcn_w1   = (const float*)d_in[9];
    const float* pcn_b1   = (const float*)d_in[10];
    const float* pcn_w2   = (const float*)d_in[11];
    const float* pcn_b2   = (const float*)d_in[12];
    const float* pq_w     = (const float*)d_in[13];
    const float* pq_b     = (const float*)d_in[14];
    const float* dec_w1   = (const float*)d_in[15];
    const float* dec_b1   = (const float*)d_in[16];
    const float* fuse_w   = (const float*)d_in[17];
    const float* fuse_b   = (const float*)d_in[18];
    const float* dec_w2   = (const float*)d_in[19];
    const float* dec_b2   = (const float*)d_in[20];

    float* out = (float*)d_out;
    float* out_logits = out;
    float* out_zl     = out_logits + (size_t)NPOS * NEMB;
    float* out_tgt    = out_zl + (size_t)BATCH * ED * 1024;
    float* out_zhq    = out_tgt + NPOS;
    float* out_dec    = out_zhq + (size_t)BATCH * ED * 1024;

    k_prep<<<128, 256>>>(z_t, z_l_pre, quant_w, quant_b, lrq_w, lrq_b, codebook, out_zl); // 0
    k_pcn1<<<BATCH*PCH, 256>>>(pcn_w1, pcn_b1);                                           // 1
    k_mega<<<256 + 4096 + 4096, 256>>>(pcn_w2, pcn_b2, out_logits,                        // 2
                                       codebook, fuse_feat, fuse_w, fuse_b);
    k_argboth<<<2*NPOS, 128>>>(out_tgt, codebook, out_zhq);                               // 3
    k_pq<<<NPOS/64, 256>>>(codebook, pq_w, pq_b);                                         // 4
    k_dec1<<<BATCH*ZCH, 256>>>(dec_w1, dec_b1, wptr);                                     // 5
    k_dec2<<<BATCH*64, 256>>>(dec_w2, dec_b2, out_dec);                                   // 6
}